// round 17
// baseline (speedup 1.0000x reference)
#include <cuda_runtime.h>
#include <cuda_bf16.h>
#include <math.h>
#include <stdint.h>

#define BS     4
#define NPTS   8192
#define KNB    32
#define CIN    64
#define CX     32
#define CF     96
#define COUT   64
#define KCONV  3072
#define PTOT   32768
#define CHUNK  4096
#define NCHUNK (PTOT / CHUNK)         // 8
#define KSPLIT 4
#define KPART  (KCONV / KSPLIT)       // 768
#define PPB    8
#define NPB    (CHUNK / PPB)          // 512 point blocks per chunk
#define GBPK   (CHUNK / 128)          // 32 gemm blocks per K-split
#define NGB    (GBPK * KSPLIT)        // 128 gemm blocks per chunk

// ---- device scratch (allocation-free; total ~149 MB, same as proven R14) ----
__device__ float g_ft[BS * NPTS * CIN];
__device__ float g_xt[BS * NPTS * 4];
__device__ __nv_bfloat16 g_Ghi[2][(size_t)CHUNK * KCONV];   // 2 x 25 MB
__device__ __nv_bfloat16 g_Glo[2][(size_t)CHUNK * KCONV];   // 2 x 25 MB
__device__ float g_part[(size_t)KSPLIT * COUT * PTOT];
__device__ float g_pre[(size_t)COUT * PTOT];
__device__ float g_scale[COUT];
__device__ float g_shift[COUT];
__device__ __nv_bfloat16 g_Whi[(size_t)COUT * KCONV];
__device__ __nv_bfloat16 g_Wlo[(size_t)COUT * KCONV];

// ===========================================================================
__device__ __forceinline__ uint32_t smem_u32(const void* p) {
    uint32_t a;
    asm("{ .reg .u64 t; cvta.to.shared.u64 t, %1; cvt.u32.u64 %0, t; }" : "=r"(a) : "l"(p));
    return a;
}
__device__ __forceinline__ void ldsm4(uint32_t* r, uint32_t addr) {
    asm volatile("ldmatrix.sync.aligned.m8n8.x4.shared.b16 {%0,%1,%2,%3}, [%4];"
                 : "=r"(r[0]), "=r"(r[1]), "=r"(r[2]), "=r"(r[3]) : "r"(addr));
}
__device__ __forceinline__ void ldsm4t(uint32_t* r, uint32_t addr) {
    asm volatile("ldmatrix.sync.aligned.m8n8.x4.trans.shared.b16 {%0,%1,%2,%3}, [%4];"
                 : "=r"(r[0]), "=r"(r[1]), "=r"(r[2]), "=r"(r[3]) : "r"(addr));
}
__device__ __forceinline__ void ldsm2(uint32_t* r, uint32_t addr) {
    asm volatile("ldmatrix.sync.aligned.m8n8.x2.shared.b16 {%0,%1}, [%2];"
                 : "=r"(r[0]), "=r"(r[1]) : "r"(addr));
}
__device__ __forceinline__ void mma_bf16(float* d, const uint32_t* a, const uint32_t* b) {
    asm volatile(
        "mma.sync.aligned.m16n8k16.row.col.f32.bf16.bf16.f32 "
        "{%0,%1,%2,%3}, {%4,%5,%6,%7}, {%8,%9}, {%0,%1,%2,%3};"
        : "+f"(d[0]), "+f"(d[1]), "+f"(d[2]), "+f"(d[3])
        : "r"(a[0]), "r"(a[1]), "r"(a[2]), "r"(a[3]), "r"(b[0]), "r"(b[1]));
}
__device__ __forceinline__ void split2(float v0, float v1, uint32_t& hi, uint32_t& lo) {
    __nv_bfloat16 h0 = __float2bfloat16_rn(v0), h1 = __float2bfloat16_rn(v1);
    float l0 = v0 - __bfloat162float(h0);
    float l1 = v1 - __bfloat162float(h1);
    __nv_bfloat16 g0 = __float2bfloat16_rn(l0), g1 = __float2bfloat16_rn(l1);
    hi = ((uint32_t)__bfloat16_as_ushort(h1) << 16) | (uint32_t)__bfloat16_as_ushort(h0);
    lo = ((uint32_t)__bfloat16_as_ushort(g1) << 16) | (uint32_t)__bfloat16_as_ushort(g0);
}

// ---------------------------------------------------------------------------
__global__ __launch_bounds__(256) void prep_w(const float* __restrict__ Wconv)
{
    int e = blockIdx.x * 256 + threadIdx.x;
    if (e >= COUT * KCONV) return;
    float w = Wconv[e];
    __nv_bfloat16 hi = __float2bfloat16_rn(w);
    g_Whi[e] = hi;
    g_Wlo[e] = __float2bfloat16_rn(w - __bfloat162float(hi));
}

__global__ __launch_bounds__(256) void transpose_f(const float* __restrict__ f)
{
    int e = blockIdx.x * 256 + threadIdx.x;
    if (e >= BS * CIN * NPTS) return;
    int n = e & (NPTS - 1);
    int c = (e >> 13) & 63;
    int b = e >> 19;
    g_ft[(((size_t)(b << 13) + n) << 6) + c] = f[e];
}

__global__ __launch_bounds__(256) void transpose_x(const float* __restrict__ x)
{
    int e = blockIdx.x * 256 + threadIdx.x;
    if (e >= BS * 3 * NPTS) return;
    int b = e / (3 * NPTS);
    int r = e - b * 3 * NPTS;
    int d = r >> 13;
    int n = r & (NPTS - 1);
    g_xt[(((b << 13) + n) << 2) + d] = x[e];
}

// ---------------------------------------------------------------------------
// Shared-memory union layouts
// ---------------------------------------------------------------------------
#define PA_PITCH 104
#define PB_PITCH 40
#define PE_PITCH 72
// point-role offsets within usm (all 16B-aligned)
#define P_AH   0
#define P_AL   6656
#define P_BH   13312
#define P_BL   15872
#define P_PEH  18432
#define P_PEL  23040
#define P_WMH  27648
#define P_WML  32256
#define P_PERM 36864
#define P_B    41088
#define P_K    41984
#define P_BM   42368
#define P_INV  42496
// gemm-role offsets
#define OFF_AHI 0
#define OFF_ALO 18432
#define OFF_WHI 36864
#define OFF_WLO 46080
#define U_SMEM  55296
#define APITCH 72
#define SPITCH 132
#define NKC (KPART / 64)

// ---------------------------------------------------------------------------
// Point body (math identical to R14-passing point_kernel; smem via usm)
// ---------------------------------------------------------------------------
__device__ void point_body(
    char* usm, int pchunk, int rbid,
    const int*   __restrict__ neigh_all,
    const float* __restrict__ Bmat,
    const float* __restrict__ kern,
    const float* __restrict__ one_pad,
    const float* __restrict__ Wmlp,
    const float* __restrict__ bmlp)
{
    const int t    = threadIdx.x;
    const int lane = t & 31;
    const int w    = t >> 5;
    const int buf  = pchunk & 1;
    const int pbase = pchunk * CHUNK;
    const int* neigh = neigh_all + (size_t)pchunk * CHUNK * KNB;

    typedef uint16_t (*AT)[PA_PITCH];
    typedef uint16_t (*BT)[PB_PITCH];
    typedef uint16_t (*ET)[PE_PITCH];
    typedef float    (*PT)[33];
    typedef float    (*CT)[32];
    AT s_Ah  = (AT)(usm + P_AH);
    AT s_Al  = (AT)(usm + P_AL);
    BT s_Bh  = (BT)(usm + P_BH);
    BT s_Bl  = (BT)(usm + P_BL);
    ET s_peh = (ET)(usm + P_PEH);
    ET s_pel = (ET)(usm + P_PEL);
    ET s_Wmh = (ET)(usm + P_WMH);
    ET s_Wml = (ET)(usm + P_WML);
    PT s_perm = (PT)(usm + P_PERM);
    CT s_B   = (CT)(usm + P_B);
    CT s_k   = (CT)(usm + P_K);
    float* s_bm  = (float*)(usm + P_BM);
    float* s_inv = (float*)(usm + P_INV);

    for (int i = t; i < 224; i += 128) s_B[i >> 5][i & 31] = Bmat[i];
    for (int i = t; i < 96;  i += 128) s_k[i >> 5][i & 31] = kern[i];
    if (t < 32) s_bm[t] = bmlp[t];
    for (int i = t; i < 2048; i += 128) {
        int o = i >> 6, f = i & 63;
        float v = Wmlp[i];
        __nv_bfloat16 h = __float2bfloat16_rn(v);
        s_Wmh[o][f] = __bfloat16_as_ushort(h);
        s_Wml[o][f] = __bfloat16_as_ushort(__float2bfloat16_rn(v - __bfloat162float(h)));
    }
    float opr[8];
    #pragma unroll
    for (int i = 0; i < 8; i++) opr[i] = one_pad[lane * 32 + (w << 3) + i];

    const int    b   = pbase >> 13;
    const float* ftb = g_ft + ((size_t)b << 19);
    const float* xtb = g_xt + ((size_t)b << 15);
    const int    p0  = rbid * PPB;

    const int kr = t >> 4;
    const int c4 = t & 15;

    const uint32_t bAh = smem_u32(usm + P_AH), bAl = smem_u32(usm + P_AL);
    const uint32_t bBh = smem_u32(usm + P_BH), bBl = smem_u32(usm + P_BL);
    const uint32_t bPh = smem_u32(usm + P_PEH), bPl = smem_u32(usm + P_PEL);
    const uint32_t bWh = smem_u32(usm + P_WMH), bWl = smem_u32(usm + P_WML);

    float4 fv[4];
    float4 xnl, xn0;
    {
        const int pb5 = p0 << 5;
        int i0 = neigh[pb5];
        int il = neigh[pb5 + lane];
        xn0 = *((const float4*)(xtb + ((size_t)i0 << 2)));
        xnl = *((const float4*)(xtb + ((size_t)il << 2)));
        #pragma unroll
        for (int r = 0; r < 4; r++) {
            int idx = neigh[pb5 + kr + r * 8];
            fv[r] = *((const float4*)(ftb + ((size_t)idx << 6) + (c4 << 2)));
        }
    }
    __syncthreads();

    const float TWO_PI = 6.283185307179586f;

    for (int ip = 0; ip < PPB; ip++) {
        const int pl = p0 + ip;

        #pragma unroll
        for (int r = 0; r < 4; r++) {
            const int k = kr + r * 8;
            uint32_t h0, l0, h1, l1;
            split2(fv[r].x, fv[r].y, h0, l0);
            split2(fv[r].z, fv[r].w, h1, l1);
            *((uint2*)&s_Ah[k][c4 << 2]) = make_uint2(h0, h1);
            *((uint2*)&s_Al[k][c4 << 2]) = make_uint2(l0, l1);
        }

        const float r0 = xnl.x - xn0.x;
        const float r1 = xnl.y - xn0.y;
        const float r2 = xnl.z - xn0.z;
        const float dis = sqrtf(fmaxf(r0 * r0 + r1 * r1 + r2 * r2, 1e-12f));

        {
            float sv[8], cv[8];
            #pragma unroll
            for (int i = 0; i < 8; i++) {
                const int m = (w << 3) + i;
                float acc = xn0.x * s_B[0][m] + xn0.y * s_B[1][m] + xn0.z * s_B[2][m]
                          + r0 * s_B[3][m] + r1 * s_B[4][m] + r2 * s_B[5][m]
                          + dis * s_B[6][m];
                __sincosf(acc * TWO_PI, &sv[i], &cv[i]);
            }
            #pragma unroll
            for (int i = 0; i < 8; i += 2) {
                uint32_t h, l;
                split2(sv[i], sv[i + 1], h, l);
                *((uint32_t*)&s_peh[lane][(w << 3) + i]) = h;
                *((uint32_t*)&s_pel[lane][(w << 3) + i]) = l;
                split2(cv[i], cv[i + 1], h, l);
                *((uint32_t*)&s_peh[lane][32 + (w << 3) + i]) = h;
                *((uint32_t*)&s_pel[lane][32 + (w << 3) + i]) = l;
            }
        }

        #pragma unroll
        for (int i = 0; i < 8; i++) {
            const int j = (w << 3) + i;
            float v = fmaxf(opr[i] + r0 * s_k[0][j] + r1 * s_k[1][j] + r2 * s_k[2][j], 0.0f);
            s_perm[lane][j] = v;
            __nv_bfloat16 h = __float2bfloat16_rn(v);
            s_Bh[j][lane] = __bfloat16_as_ushort(h);
            s_Bl[j][lane] = __bfloat16_as_ushort(__float2bfloat16_rn(v - __bfloat162float(h)));
        }
        __syncthreads();   // sync1

        // MLP via HMMA
        {
            float d0[4] = {0.f, 0.f, 0.f, 0.f};
            float d1[4] = {0.f, 0.f, 0.f, 0.f};
            const int arow = lane & 15;
            const int acol = (lane >> 4) << 3;
            const int bl15 = lane & 15;
            const uint32_t brow = (uint32_t)((w << 3) + (bl15 & 7));
            const uint32_t bkof = (uint32_t)(((bl15 >> 3) & 1) << 3);
            #pragma unroll
            for (int kh = 0; kh < 4; kh++) {
                const uint32_t boff = (brow * PE_PITCH + kh * 16 + bkof) * 2;
                uint32_t bh[2], bl[2];
                ldsm2(bh, bWh + boff);
                ldsm2(bl, bWl + boff);
                #pragma unroll
                for (int mt = 0; mt < 2; mt++) {
                    uint32_t ah[4], al[4];
                    const uint32_t aoff = (uint32_t)((mt * 16 + arow) * PE_PITCH + kh * 16 + acol) * 2;
                    ldsm4(ah, bPh + aoff);
                    ldsm4(al, bPl + aoff);
                    float* d = mt ? d1 : d0;
                    mma_bf16(d, ah, bh);
                    mma_bf16(d, ah, bl);
                    mma_bf16(d, al, bh);
                }
            }
            const int o = (w << 3) + ((lane & 3) << 1);
            const float bb0 = s_bm[o], bb1 = s_bm[o + 1];
            #pragma unroll
            for (int mt = 0; mt < 2; mt++) {
                const float* d = mt ? d1 : d0;
                const int krow = mt * 16 + (lane >> 2);
                uint32_t h, l;
                split2(d[0] + bb0, d[1] + bb1, h, l);
                *((uint32_t*)&s_Ah[krow][64 + o]) = h;
                *((uint32_t*)&s_Al[krow][64 + o]) = l;
                split2(d[2] + bb0, d[3] + bb1, h, l);
                *((uint32_t*)&s_Ah[krow + 8][64 + o]) = h;
                *((uint32_t*)&s_Al[krow + 8][64 + o]) = l;
            }
        }

        if (t < 32) {
            float s = 0.f;
            #pragma unroll
            for (int k = 0; k < 32; k++) s += s_perm[k][t];
            s_inv[t] = 1.0f / (s + 1e-6f);
        }

        if (ip + 1 < PPB) {
            const int pb5 = (pl + 1) << 5;
            int i0 = neigh[pb5];
            int il = neigh[pb5 + lane];
            xn0 = *((const float4*)(xtb + ((size_t)i0 << 2)));
            xnl = *((const float4*)(xtb + ((size_t)il << 2)));
            #pragma unroll
            for (int r = 0; r < 4; r++) {
                int idx = neigh[pb5 + kr + r * 8];
                fv[r] = *((const float4*)(ftb + ((size_t)idx << 6) + (c4 << 2)));
            }
        }
        __syncthreads();   // sync2

        // contraction via HMMA: warps 0..2
        if (w < 3) {
            float acc[2][4][4];
            #pragma unroll
            for (int mt = 0; mt < 2; mt++)
                #pragma unroll
                for (int nt = 0; nt < 4; nt++)
                    #pragma unroll
                    for (int i = 0; i < 4; i++) acc[mt][nt][i] = 0.f;

            const uint32_t a_krow = (uint32_t)((lane & 7) + ((lane >> 4) << 3));
            const uint32_t a_cblk = (uint32_t)(((lane >> 3) & 1) << 3);
            const uint32_t b_n    = (uint32_t)((lane & 7) + (((lane >> 4) & 1) << 3));
            const uint32_t b_koff = (uint32_t)(((lane >> 3) & 1) << 3);

            #pragma unroll
            for (int kh = 0; kh < 2; kh++) {
                const uint32_t k0 = kh * 16;
                #pragma unroll
                for (int mt = 0; mt < 2; mt++) {
                    uint32_t ah[4], al[4];
                    const uint32_t cb = (uint32_t)(w * 32 + mt * 16) + a_cblk;
                    const uint32_t aoff = ((k0 + a_krow) * PA_PITCH + cb) * 2;
                    ldsm4t(ah, bAh + aoff);
                    ldsm4t(al, bAl + aoff);
                    #pragma unroll
                    for (int bt = 0; bt < 2; bt++) {
                        uint32_t bh[4], bl[4];
                        const uint32_t boff = (((uint32_t)(bt * 16) + b_n) * PB_PITCH + k0 + b_koff) * 2;
                        ldsm4(bh, bBh + boff);
                        ldsm4(bl, bBl + boff);
                        #pragma unroll
                        for (int hh = 0; hh < 2; hh++) {
                            float* d = acc[mt][bt * 2 + hh];
                            mma_bf16(d, ah, bh + hh * 2);
                            mma_bf16(d, ah, bl + hh * 2);
                            mma_bf16(d, al, bh + hh * 2);
                        }
                    }
                }
            }

            __nv_bfloat16* gh = g_Ghi[buf] + (size_t)pl * KCONV;
            __nv_bfloat16* gl = g_Glo[buf] + (size_t)pl * KCONV;
            #pragma unroll
            for (int nt = 0; nt < 4; nt++) {
                const int j = nt * 8 + ((lane & 3) << 1);
                const float i0 = s_inv[j], i1 = s_inv[j + 1];
                #pragma unroll
                for (int mt = 0; mt < 2; mt++) {
                    const float* d = acc[mt][nt];
                    const int c0 = w * 32 + mt * 16 + (lane >> 2);
                    uint32_t h, l;
                    split2(d[0] * i0, d[1] * i1, h, l);
                    *((uint32_t*)(gh + c0 * 32 + j)) = h;
                    *((uint32_t*)(gl + c0 * 32 + j)) = l;
                    split2(d[2] * i0, d[3] * i1, h, l);
                    *((uint32_t*)(gh + (c0 + 8) * 32 + j)) = h;
                    *((uint32_t*)(gl + (c0 + 8) * 32 + j)) = l;
                }
            }
        }
        __syncthreads();   // sync3
    }
}

// ---------------------------------------------------------------------------
// Gemm body (R13-passing single-stage; pre-split G, buf-indexed)
// ---------------------------------------------------------------------------
__device__ void gemm_body(char* usm, int gchunk, int rbid)
{
    __nv_bfloat16* Ahi = (__nv_bfloat16*)(usm + OFF_AHI);
    __nv_bfloat16* Alo = (__nv_bfloat16*)(usm + OFF_ALO);
    __nv_bfloat16* Whs = (__nv_bfloat16*)(usm + OFF_WHI);
    __nv_bfloat16* Wls = (__nv_bfloat16*)(usm + OFF_WLO);
    float*         stg = (float*)usm;
    const uint32_t sb  = smem_u32(usm);

    const int t    = threadIdx.x;
    const int lane = t & 31;
    const int w    = t >> 5;
    const int buf  = gchunk & 1;
    const int pbase = gchunk * CHUNK;
    const int pl0  = (rbid & (GBPK - 1)) * 128;
    const int kh   = rbid / GBPK;
    const int kb   = kh * KPART;

    float acc[2][8][4];
    #pragma unroll
    for (int mt = 0; mt < 2; mt++)
        #pragma unroll
        for (int nt = 0; nt < 8; nt++)
            #pragma unroll
            for (int i = 0; i < 4; i++) acc[mt][nt][i] = 0.f;

    const int wrow  = t >> 1;
    const int whalf = t & 1;

    const int a_row  = (lane & 15);
    const int a_col  = (lane >> 4) << 3;
    const int b_n    = (lane & 7) + (((lane >> 4) & 1) << 3);
    const int b_koff = ((lane >> 3) & 1) << 3;

    for (int kc = 0; kc < NKC; kc++) {
        {
            const uint4* sh = (const uint4*)(g_Ghi[buf] + (size_t)(pl0 + t) * KCONV + kb + kc * 64);
            const uint4* sl = (const uint4*)(g_Glo[buf] + (size_t)(pl0 + t) * KCONV + kb + kc * 64);
            #pragma unroll
            for (int j = 0; j < 8; j++) {
                *((uint4*)(Ahi + t * APITCH + j * 8)) = sh[j];
                *((uint4*)(Alo + t * APITCH + j * 8)) = sl[j];
            }
        }
        {
            size_t off = (size_t)wrow * KCONV + kb + kc * 64 + whalf * 32;
            const uint4* wh = (const uint4*)(g_Whi + off);
            const uint4* wl = (const uint4*)(g_Wlo + off);
            #pragma unroll
            for (int i = 0; i < 4; i++) {
                *((uint4*)(Whs + wrow * APITCH + whalf * 32 + i * 8)) = wh[i];
                *((uint4*)(Wls + wrow * APITCH + whalf * 32 + i * 8)) = wl[i];
            }
        }
        __syncthreads();

        #pragma unroll
        for (int s = 0; s < 4; s++) {
            const int k0 = s * 16;
            uint32_t ah[2][4], al[2][4];
            #pragma unroll
            for (int mt = 0; mt < 2; mt++) {
                int row = w * 32 + mt * 16 + a_row;
                ldsm4(ah[mt], sb + OFF_AHI + (uint32_t)(row * APITCH + a_col + k0) * 2);
                ldsm4(al[mt], sb + OFF_ALO + (uint32_t)(row * APITCH + a_col + k0) * 2);
            }
            #pragma unroll
            for (int np = 0; np < 4; np++) {
                int n = np * 16 + b_n;
                uint32_t bh[4], bl[4];
                ldsm4(bh, sb + OFF_WHI + (uint32_t)(n * APITCH + k0 + b_koff) * 2);
                ldsm4(bl, sb + OFF_WLO + (uint32_t)(n * APITCH + k0 + b_koff) * 2);
                #pragma unroll
                for (int mt = 0; mt < 2; mt++) {
                    #pragma unroll
                    for (int hh = 0; hh < 2; hh++) {
                        float* d = acc[mt][np * 2 + hh];
                        mma_bf16(d, ah[mt], bh + hh * 2);
                        mma_bf16(d, ah[mt], bl + hh * 2);
                        mma_bf16(d, al[mt], bh + hh * 2);
                    }
                }
            }
        }
        __syncthreads();
    }

    const int lr  = lane >> 2;
    const int lc2 = (lane & 3) << 1;
    #pragma unroll
    for (int mt = 0; mt < 2; mt++) {
        int row0 = w * 32 + mt * 16 + lr;
        #pragma unroll
        for (int nt = 0; nt < 8; nt++) {
            int col = nt * 8 + lc2;
            stg[col * SPITCH + row0]           = acc[mt][nt][0];
            stg[(col + 1) * SPITCH + row0]     = acc[mt][nt][1];
            stg[col * SPITCH + row0 + 8]       = acc[mt][nt][2];
            stg[(col + 1) * SPITCH + row0 + 8] = acc[mt][nt][3];
        }
    }
    __syncthreads();
    for (int i = t; i < 2048; i += 128) {
        int o = i >> 5, q = i & 31;
        float4 v = *((const float4*)(stg + o * SPITCH + q * 4));
        *((float4*)(g_part + ((size_t)kh * COUT + o) * PTOT + pbase + pl0 + q * 4)) = v;
    }
}

// ---------------------------------------------------------------------------
// Fused kernel: mode 0 = point-only, 1 = mixed (4:1 interleave), 2 = gemm-only
// ---------------------------------------------------------------------------
__global__ __launch_bounds__(128) void fused_kernel(
    int mode, int pchunk, int gchunk,
    const int*   __restrict__ neigh,
    const float* __restrict__ Bmat,
    const float* __restrict__ kern,
    const float* __restrict__ one_pad,
    const float* __restrict__ Wmlp,
    const float* __restrict__ bmlp)
{
    extern __shared__ char usm[];
    int role, rbid;
    if (mode == 0)      { role = 0; rbid = blockIdx.x; }
    else if (mode == 2) { role = 1; rbid = blockIdx.x; }
    else {
        int m = blockIdx.x % 5;
        if (m < 4) { role = 0; rbid = (blockIdx.x / 5) * 4 + m; }
        else       { role = 1; rbid = blockIdx.x / 5; }
    }
    if (role == 0) point_body(usm, pchunk, rbid, neigh, Bmat, kern, one_pad, Wmlp, bmlp);
    else           gemm_body(usm, gchunk, rbid);
}

// ---------------------------------------------------------------------------
__global__ __launch_bounds__(256) void stats_kernel(
    const float* __restrict__ bconv,
    const float* __restrict__ gamma, const float* __restrict__ beta)
{
    const int o = blockIdx.x;
    const int t = threadIdx.x;
    const float4* r0 = (const float4*)(g_part + ((size_t)0 * COUT + o) * PTOT);
    const float4* r1 = (const float4*)(g_part + ((size_t)1 * COUT + o) * PTOT);
    const float4* r2 = (const float4*)(g_part + ((size_t)2 * COUT + o) * PTOT);
    const float4* r3 = (const float4*)(g_part + ((size_t)3 * COUT + o) * PTOT);
    float4*       pr = (float4*)(g_pre + (size_t)o * PTOT);
    const float bb = bconv[o];

    float s = 0.f, s2 = 0.f;
    for (int i = t; i < PTOT / 4; i += 256) {
        float4 a = r0[i], b = r1[i], c = r2[i], d = r3[i];
        float4 v;
        v.x = a.x + b.x + c.x + d.x + bb;
        v.y = a.y + b.y + c.y + d.y + bb;
        v.z = a.z + b.z + c.z + d.z + bb;
        v.w = a.w + b.w + c.w + d.w + bb;
        pr[i] = v;
        s  += v.x + v.y + v.z + v.w;
        s2 += v.x * v.x + v.y * v.y + v.z * v.z + v.w * v.w;
    }
    __shared__ float rs[256], rs2[256];
    rs[t] = s; rs2[t] = s2;
    __syncthreads();
    for (int st = 128; st > 0; st >>= 1) {
        if (t < st) { rs[t] += rs[t + st]; rs2[t] += rs2[t + st]; }
        __syncthreads();
    }
    if (t == 0) {
        float mean = rs[0] * (1.0f / PTOT);
        float var  = rs2[0] * (1.0f / PTOT) - mean * mean;
        float inv  = rsqrtf(var + 1e-5f);
        float sc   = gamma[o] * inv;
        g_scale[o] = sc;
        g_shift[o] = beta[o] - mean * sc;
    }
}

// ---------------------------------------------------------------------------
__global__ __launch_bounds__(256) void norm_kernel(float* __restrict__ out)
{
    int e = blockIdx.x * 256 + threadIdx.x;
    if (e >= BS * COUT * NPTS / 4) return;
    int nq = e & (NPTS / 4 - 1);
    int o  = (e >> 11) & 63;
    int b  = e >> 17;
    float4 v = *((const float4*)(g_pre + (size_t)o * PTOT + (b << 13)) + nq);
    float sc = g_scale[o], sh = g_shift[o];
    float4 r = make_float4(v.x * sc + sh, v.y * sc + sh, v.z * sc + sh, v.w * sc + sh);
    *((float4*)out + e) = r;
}

// ---------------------------------------------------------------------------
extern "C" void kernel_launch(void* const* d_in, const int* in_sizes, int n_in,
                              void* d_out, int out_size)
{
    const float* x     = (const float*)d_in[0];
    const float* feat  = (const float*)d_in[1];
    const int*   neigh = (const int*)  d_in[2];
    const float* Bmat  = (const float*)d_in[3];
    const float* kern  = (const float*)d_in[4];
    const float* onep  = (const float*)d_in[5];
    const float* Wmlp  = (const float*)d_in[6];
    const float* bmlp  = (const float*)d_in[7];
    const float* Wconv = (const float*)d_in[8];
    const float* bconv = (const float*)d_in[9];
    const float* gamma = (const float*)d_in[10];
    const float* beta  = (const float*)d_in[11];
    float* out = (float*)d_out;

    cudaFuncSetAttribute(fused_kernel, cudaFuncAttributeMaxDynamicSharedMemorySize, U_SMEM);

    prep_w<<<(COUT * KCONV + 255) / 256, 256>>>(Wconv);
    transpose_f<<<(BS * CIN * NPTS + 255) / 256, 256>>>(feat);
    transpose_x<<<(BS * 3 * NPTS + 255) / 256, 256>>>(x);

    // software pipeline, single stream: point(ch) co-runs with gemm(ch-1)
    fused_kernel<<<NPB, 128, U_SMEM>>>(0, 0, -1, neigh, Bmat, kern, onep, Wmlp, bmlp);
    for (int ch = 1; ch < NCHUNK; ch++)
        fused_kernel<<<NPB + NGB, 128, U_SMEM>>>(1, ch, ch - 1,
                                                 neigh, Bmat, kern, onep, Wmlp, bmlp);
    fused_kernel<<<NGB, 128, U_SMEM>>>(2, -1, NCHUNK - 1,
                                       neigh, Bmat, kern, onep, Wmlp, bmlp);

    stats_kernel<<<COUT, 256>>>(bconv, gamma, beta);
    norm_kernel<<<(BS * COUT * NPTS / 4 + 255) / 256, 256>>>(out);
}